// round 1
// baseline (speedup 1.0000x reference)
#include <cuda_runtime.h>
#include <math.h>

// Problem constants
#define B_ 256
#define N_ 1024
#define H_ 256
#define K_ 5
#define NEG_SLOPE 0.01f

// Scratch: per-node sort key (max over channels), -inf for masked nodes.
__device__ float g_key[B_ * N_];

static __device__ __forceinline__ float neg_inf() {
    return __int_as_float(0xff800000);
}

// ---------------------------------------------------------------------------
// Kernel 1: key[b,n] = max_h h[b,n,:]  (or -inf if n >= n_nodes[b])
// One warp per node; masked nodes skip the 1KB read entirely.
// ---------------------------------------------------------------------------
__global__ void __launch_bounds__(256)
node_max_kernel(const float* __restrict__ h, const int* __restrict__ n_nodes) {
    int gw   = (blockIdx.x * 256 + threadIdx.x) >> 5;   // global warp = node id
    int lane = threadIdx.x & 31;
    int b = gw >> 10;          // N_ = 1024
    int n = gw & (N_ - 1);

    if (n >= __ldg(&n_nodes[b])) {
        if (lane == 0) g_key[gw] = neg_inf();
        return;
    }

    const float4* p = reinterpret_cast<const float4*>(h) + (size_t)gw * (H_ / 4);
    float4 a = p[lane];
    float4 c = p[lane + 32];
    float m = fmaxf(fmaxf(fmaxf(a.x, a.y), fmaxf(a.z, a.w)),
                    fmaxf(fmaxf(c.x, c.y), fmaxf(c.z, c.w)));
#pragma unroll
    for (int o = 16; o; o >>= 1)
        m = fmaxf(m, __shfl_xor_sync(0xffffffffu, m, o));
    if (lane == 0) g_key[gw] = m;
}

// ---------------------------------------------------------------------------
// Kernel 2: per-batch top-5, per-selected-node ascending sort (bitonic, 256),
// attention logits + softmax over K, weighted sum -> out[b, :]
// One block (256 threads) per batch.
// ---------------------------------------------------------------------------
__global__ void __launch_bounds__(256)
pool_attn_kernel(const float* __restrict__ h,
                 const float* __restrict__ q,
                 const float* __restrict__ W,
                 float* __restrict__ out) {
    __shared__ float s_key[N_];          // 4 KB
    __shared__ float s_vred[256];        // reduction values
    __shared__ int   s_ired[256];        // reduction indices
    __shared__ float s_sort[H_];         // sort workspace
    __shared__ float s_sel[K_][H_];      // 5 KB: sorted selected rows
    __shared__ float s_logit[K_];
    __shared__ int   s_tidx[K_];
    __shared__ float s_tval[K_];
    __shared__ float s_cb;

    const int b = blockIdx.x;
    const int t = threadIdx.x;
    const float NI = neg_inf();

    // ---- load keys for this batch ----
    for (int i = t; i < N_; i += 256) s_key[i] = g_key[b * N_ + i];
    __syncthreads();

    // ---- top-K argmax (lower index wins ties; only matters for -inf ties,
    //      which are zeroed downstream anyway) ----
    for (int k = 0; k < K_; k++) {
        float best = NI;
        int   bi   = N_;
        for (int i = t; i < N_; i += 256) {
            float v = s_key[i];
            if (v > best || (v == best && i < bi)) { best = v; bi = i; }
        }
        s_vred[t] = best;
        s_ired[t] = bi;
        __syncthreads();
        for (int s = 128; s; s >>= 1) {
            if (t < s) {
                float ov = s_vred[t + s];
                int   oi = s_ired[t + s];
                if (ov > s_vred[t] || (ov == s_vred[t] && oi < s_ired[t])) {
                    s_vred[t] = ov;
                    s_ired[t] = oi;
                }
            }
            __syncthreads();
        }
        if (t == 0) {
            s_tidx[k] = s_ired[0];
            s_tval[k] = s_vred[0];
            if (s_ired[0] < N_) s_key[s_ired[0]] = NI;  // remove from pool
        }
        __syncthreads();
    }

    // ---- c_b = dot(q[b,:], W[H:2H]) ----
    s_vred[t] = q[b * H_ + t] * W[H_ + t];
    __syncthreads();
    for (int s = 128; s; s >>= 1) {
        if (t < s) s_vred[t] += s_vred[t + s];
        __syncthreads();
    }
    if (t == 0) s_cb = s_vred[0];
    __syncthreads();
    const float cb = s_cb;

    // ---- per-selected-node: sort ascending, dot with W[:H] ----
    for (int k = 0; k < K_; k++) {
        bool valid = (s_tval[k] > NI);   // finite max <=> real node
        float v = 0.0f;
        if (valid)
            v = h[((size_t)b * N_ + s_tidx[k]) * H_ + t];
        s_sort[t] = v;
        __syncthreads();

        // bitonic sort, 256 elements, ascending
        for (int kk = 2; kk <= 256; kk <<= 1) {
            for (int j = kk >> 1; j > 0; j >>= 1) {
                int ix = t ^ j;
                if (ix > t) {
                    float a = s_sort[t];
                    float c = s_sort[ix];
                    bool up = ((t & kk) == 0);
                    if ((a > c) == up) { s_sort[t] = c; s_sort[ix] = a; }
                }
                __syncthreads();
            }
        }

        s_sel[k][t] = s_sort[t];

        // dot(sorted, W[:H])  (zeros if invalid -> dot 0, matching reference)
        s_vred[t] = s_sort[t] * W[t];
        __syncthreads();
        for (int s = 128; s; s >>= 1) {
            if (t < s) s_vred[t] += s_vred[t + s];
            __syncthreads();
        }
        if (t == 0) {
            float x = s_vred[0] + cb;
            s_logit[k] = (x >= 0.0f) ? x : NEG_SLOPE * x;
        }
        __syncthreads();
    }

    // ---- softmax over K and weighted sum (each thread owns channel t) ----
    float lm = s_logit[0];
#pragma unroll
    for (int k = 1; k < K_; k++) lm = fmaxf(lm, s_logit[k]);
    float es = 0.0f;
    float e[K_];
#pragma unroll
    for (int k = 0; k < K_; k++) { e[k] = __expf(s_logit[k] - lm); es += e[k]; }
    float inv = 1.0f / es;
    float acc = 0.0f;
#pragma unroll
    for (int k = 0; k < K_; k++) acc += (e[k] * inv) * s_sel[k][t];

    out[b * H_ + t] = acc;
}

extern "C" void kernel_launch(void* const* d_in, const int* in_sizes, int n_in,
                              void* d_out, int out_size) {
    const float* h  = (const float*)d_in[0];           // [B, N, H]
    const int*   nn = (const int*)d_in[1];             // [B]
    const float* q  = (const float*)d_in[2];           // [B, H]
    const float* W  = (const float*)d_in[3];           // [1, 2H]
    float*       o  = (float*)d_out;                   // [B, H]

    (void)in_sizes; (void)n_in; (void)out_size;

    // Kernel 1: B*N nodes, one warp each, 8 warps/block
    node_max_kernel<<<(B_ * N_) / 8, 256>>>(h, nn);
    // Kernel 2: one block per batch
    pool_attn_kernel<<<B_, 256>>>(h, q, W, o);
}

// round 4
// speedup vs baseline: 1.5304x; 1.5304x over previous
#include <cuda_runtime.h>
#include <math.h>

// Problem constants
#define B_ 256
#define N_ 1024
#define H_ 256
#define K_ 5
#define NEG_SLOPE 0.01f
#define FULLMASK 0xffffffffu

// Scratch: per-node sort key (max over channels), -inf for masked nodes.
__device__ float g_key[B_ * N_];

static __device__ __forceinline__ float neg_inf() {
    return __int_as_float(0xff800000);
}

// ---------------------------------------------------------------------------
// Kernel 1: key[b,n] = max_h h[b,n,:]  (or -inf if n >= n_nodes[b])
// One warp per node; masked nodes skip the 1KB read entirely.
// ---------------------------------------------------------------------------
__global__ void __launch_bounds__(256)
node_max_kernel(const float* __restrict__ h, const int* __restrict__ n_nodes) {
    int gw   = (blockIdx.x * 256 + threadIdx.x) >> 5;   // global warp = node id
    int lane = threadIdx.x & 31;
    int b = gw >> 10;          // N_ = 1024
    int n = gw & (N_ - 1);

    if (n >= __ldg(&n_nodes[b])) {
        if (lane == 0) g_key[gw] = neg_inf();
        return;
    }

    const float4* p = reinterpret_cast<const float4*>(h) + (size_t)gw * (H_ / 4);
    float4 a = p[lane];
    float4 c = p[lane + 32];
    float m = fmaxf(fmaxf(fmaxf(a.x, a.y), fmaxf(a.z, a.w)),
                    fmaxf(fmaxf(c.x, c.y), fmaxf(c.z, c.w)));
#pragma unroll
    for (int o = 16; o; o >>= 1)
        m = fmaxf(m, __shfl_xor_sync(FULLMASK, m, o));
    if (lane == 0) g_key[gw] = m;
}

// ---------------------------------------------------------------------------
// Kernel 2 (warp-centric, 3 block barriers total):
//  - all warps cooperatively load the 1024 keys into shared
//  - warp 0: 5 sequential argmax passes (lowest-index tie-break, matching
//    jax.lax.top_k); warp 5: cb = dot(q, W[H:2H])
//  - warps 0..4: register bitonic sort (8 elems/lane) of their selected row,
//    shuffle-reduce dot with W[:H], leaky-relu logit
//  - all threads: softmax over K + weighted sum
// ---------------------------------------------------------------------------
__global__ void __launch_bounds__(256)
pool_attn_kernel(const float* __restrict__ h,
                 const float* __restrict__ q,
                 const float* __restrict__ W,
                 float* __restrict__ out) {
    __shared__ float s_key[N_];          // 4 KB
    __shared__ float s_sel[K_][H_];      // 5 KB: sorted selected rows
    __shared__ float s_logit[K_];
    __shared__ int   s_tidx[K_];
    __shared__ float s_tval[K_];
    __shared__ float s_cb;

    const int b    = blockIdx.x;
    const int t    = threadIdx.x;
    const int wid  = t >> 5;
    const int lane = t & 31;
    const float NI = neg_inf();

    // ---- load keys for this batch (all 8 warps, coalesced) ----
#pragma unroll
    for (int i = 0; i < 4; i++)
        s_key[t + i * 256] = g_key[b * N_ + t + i * 256];
    __syncthreads();   // barrier A

    if (wid == 0) {
        // ---- K sequential argmax passes, lowest index wins ties ----
        for (int k = 0; k < K_; k++) {
            float bv = NI;
            int   bi = N_;
#pragma unroll
            for (int jj = 0; jj < 32; jj++) {
                int   i = lane + (jj << 5);       // conflict-free LDS
                float v = s_key[i];
                if (v > bv || (v == bv && i < bi)) { bv = v; bi = i; }
            }
#pragma unroll
            for (int o = 16; o; o >>= 1) {
                float ov = __shfl_xor_sync(FULLMASK, bv, o);
                int   oi = __shfl_xor_sync(FULLMASK, bi, o);
                if (ov > bv || (ov == bv && oi < bi)) { bv = ov; bi = oi; }
            }
            // all lanes now agree on (bv, bi); lane 0 records + removes
            if (lane == 0) {
                s_tval[k] = bv;
                s_tidx[k] = bi;
                s_key[bi] = NI;
            }
            __syncwarp();
        }
    } else if (wid == 5) {
        // ---- cb = dot(q[b,:], W[H:2H]) ----
        float s = 0.0f;
#pragma unroll
        for (int r = 0; r < 8; r++) {
            int i = (lane << 3) + r;
            s += q[b * H_ + i] * W[H_ + i];
        }
#pragma unroll
        for (int o = 16; o; o >>= 1)
            s += __shfl_xor_sync(FULLMASK, s, o);
        if (lane == 0) s_cb = s;
    }
    __syncthreads();   // barrier B

    // ---- warps 0..4: sort selected row k=wid, dot with W[:H] ----
    if (wid < K_) {
        const int k = wid;
        bool valid  = (s_tval[k] > NI);
        int  node   = s_tidx[k];
        const float* row = h + ((size_t)b * N_ + node) * H_;

        // element v = lane*8 + r lives in val[r] of this lane
        float val[8];
#pragma unroll
        for (int r = 0; r < 8; r++)
            val[r] = valid ? row[(lane << 3) + r] : 0.0f;

        // ---- register bitonic sort, 256 elements, ascending ----
#pragma unroll
        for (int kk = 2; kk <= 256; kk <<= 1) {
#pragma unroll
            for (int j = kk >> 1; j > 0; j >>= 1) {
                if (j >= 8) {
                    int  ld  = j >> 3;
                    bool asc = (((lane << 3) & kk) == 0);
                    bool low = ((lane & ld) == 0);
#pragma unroll
                    for (int r = 0; r < 8; r++) {
                        float other = __shfl_xor_sync(FULLMASK, val[r], ld);
                        val[r] = (low == asc) ? fminf(val[r], other)
                                              : fmaxf(val[r], other);
                    }
                } else {
#pragma unroll
                    for (int r = 0; r < 8; r++) {
                        if ((r & j) == 0) {
                            int  r2  = r | j;
                            bool asc = ((((lane << 3) | r) & kk) == 0);
                            float a = val[r], c = val[r2];
                            float lo = fminf(a, c), hi = fmaxf(a, c);
                            val[r]  = asc ? lo : hi;
                            val[r2] = asc ? hi : lo;
                        }
                    }
                }
            }
        }

        // store sorted row + dot with W[:H]
        float s = 0.0f;
#pragma unroll
        for (int r = 0; r < 8; r++) {
            int i = (lane << 3) + r;
            s_sel[k][i] = val[r];
            s += val[r] * W[i];
        }
#pragma unroll
        for (int o = 16; o; o >>= 1)
            s += __shfl_xor_sync(FULLMASK, s, o);
        if (lane == 0) {
            float x = s + s_cb;
            s_logit[k] = (x >= 0.0f) ? x : NEG_SLOPE * x;
        }
    }
    __syncthreads();   // barrier C

    // ---- softmax over K and weighted sum (thread t owns channel t) ----
    float lg[K_];
#pragma unroll
    for (int k = 0; k < K_; k++) lg[k] = s_logit[k];
    float lm = lg[0];
#pragma unroll
    for (int k = 1; k < K_; k++) lm = fmaxf(lm, lg[k]);
    float es = 0.0f;
    float e[K_];
#pragma unroll
    for (int k = 0; k < K_; k++) { e[k] = __expf(lg[k] - lm); es += e[k]; }
    float inv = 1.0f / es;
    float acc = 0.0f;
#pragma unroll
    for (int k = 0; k < K_; k++) acc += (e[k] * inv) * s_sel[k][t];

    out[b * H_ + t] = acc;
}

extern "C" void kernel_launch(void* const* d_in, const int* in_sizes, int n_in,
                              void* d_out, int out_size) {
    const float* h  = (const float*)d_in[0];           // [B, N, H]
    const int*   nn = (const int*)d_in[1];             // [B]
    const float* q  = (const float*)d_in[2];           // [B, H]
    const float* W  = (const float*)d_in[3];           // [1, 2H]
    float*       o  = (float*)d_out;                   // [B, H]

    (void)in_sizes; (void)n_in; (void)out_size;

    node_max_kernel<<<(B_ * N_) / 8, 256>>>(h, nn);
    pool_attn_kernel<<<B_, 256>>>(h, q, W, o);
}

// round 5
// speedup vs baseline: 1.7154x; 1.1209x over previous
#include <cuda_runtime.h>
#include <math.h>

// Problem constants
#define B_ 256
#define N_ 1024
#define H_ 256
#define K_ 5
#define NEG_SLOPE 0.01f
#define FULLMASK 0xffffffffu

// Scratch: per-node sort key (max over channels), -inf for masked nodes.
__device__ float g_key[B_ * N_];

static __device__ __forceinline__ float neg_inf() {
    return __int_as_float(0xff800000);
}

// ---------------------------------------------------------------------------
// Kernel 1: key[b,n] = max_h h[b,n,:]  (or -inf if n >= n_nodes[b])
// One warp per 4 nodes; all 8 LDG.128 front-batched for MLP=8 (4KB/warp
// in flight). Masked nodes produce -inf without loading. Lane 0 writes the
// 4 keys as one float4.
// ---------------------------------------------------------------------------
__global__ void __launch_bounds__(256)
node_max_kernel(const float* __restrict__ h, const int* __restrict__ n_nodes) {
    const int gw   = (blockIdx.x * 256 + threadIdx.x) >> 5;  // warp id
    const int lane = threadIdx.x & 31;
    const int base = gw << 2;                 // first of 4 nodes (same batch)
    const int b    = base >> 10;              // N_ = 1024
    const int n0   = base & (N_ - 1);
    const int nn   = __ldg(&n_nodes[b]);
    const float NI = neg_inf();

    const float4* p = reinterpret_cast<const float4*>(h) + (size_t)base * (H_ / 4);

    // front-batch all loads (up to 8 LDG.128 per lane)
    float4 va[4], vc[4];
    bool valid[4];
#pragma unroll
    for (int j = 0; j < 4; j++) {
        valid[j] = (n0 + j) < nn;
        if (valid[j]) {
            va[j] = p[(j << 6) + lane];
            vc[j] = p[(j << 6) + lane + 32];
        }
    }

    float m[4];
#pragma unroll
    for (int j = 0; j < 4; j++) {
        if (valid[j]) {
            m[j] = fmaxf(fmaxf(fmaxf(va[j].x, va[j].y), fmaxf(va[j].z, va[j].w)),
                         fmaxf(fmaxf(vc[j].x, vc[j].y), fmaxf(vc[j].z, vc[j].w)));
        } else {
            m[j] = NI;
        }
    }

    // four interleaved butterfly reductions
#pragma unroll
    for (int o = 16; o; o >>= 1) {
#pragma unroll
        for (int j = 0; j < 4; j++)
            m[j] = fmaxf(m[j], __shfl_xor_sync(FULLMASK, m[j], o));
    }

    if (lane == 0) {
        float4 r = make_float4(m[0], m[1], m[2], m[3]);
        *reinterpret_cast<float4*>(&g_key[base]) = r;
    }
}

// ---------------------------------------------------------------------------
// Kernel 2 (warp-centric, 3 block barriers total):
//  - all warps cooperatively load the 1024 keys into shared (float4)
//  - warp 0: 5 sequential argmax passes (lowest-index tie-break, matching
//    jax.lax.top_k); warp 5: cb = dot(q, W[H:2H])
//  - warps 0..4: register bitonic sort (8 elems/lane) of their selected row,
//    shuffle-reduce dot with W[:H], leaky-relu logit
//  - all threads: softmax over K + weighted sum
// ---------------------------------------------------------------------------
__global__ void __launch_bounds__(256)
pool_attn_kernel(const float* __restrict__ h,
                 const float* __restrict__ q,
                 const float* __restrict__ W,
                 float* __restrict__ out) {
    __shared__ float s_key[N_];          // 4 KB
    __shared__ float s_sel[K_][H_];      // 5 KB: sorted selected rows
    __shared__ float s_logit[K_];
    __shared__ int   s_tidx[K_];
    __shared__ float s_tval[K_];
    __shared__ float s_cb;

    const int b    = blockIdx.x;
    const int t    = threadIdx.x;
    const int wid  = t >> 5;
    const int lane = t & 31;
    const float NI = neg_inf();

    // ---- load keys for this batch (one float4 per thread, coalesced) ----
    reinterpret_cast<float4*>(s_key)[t] =
        reinterpret_cast<const float4*>(g_key + b * N_)[t];
    __syncthreads();   // barrier A

    if (wid == 0) {
        // ---- K sequential argmax passes, lowest index wins ties ----
        for (int k = 0; k < K_; k++) {
            float bv = NI;
            int   bi = N_;
#pragma unroll
            for (int jj = 0; jj < 32; jj++) {
                int   i = lane + (jj << 5);       // conflict-free LDS
                float v = s_key[i];
                if (v > bv || (v == bv && i < bi)) { bv = v; bi = i; }
            }
#pragma unroll
            for (int o = 16; o; o >>= 1) {
                float ov = __shfl_xor_sync(FULLMASK, bv, o);
                int   oi = __shfl_xor_sync(FULLMASK, bi, o);
                if (ov > bv || (ov == bv && oi < bi)) { bv = ov; bi = oi; }
            }
            // all lanes now agree on (bv, bi); lane 0 records + removes
            if (lane == 0) {
                s_tval[k] = bv;
                s_tidx[k] = bi;
                s_key[bi] = NI;
            }
            __syncwarp();
        }
    } else if (wid == 5) {
        // ---- cb = dot(q[b,:], W[H:2H]) ----
        float s = 0.0f;
#pragma unroll
        for (int r = 0; r < 8; r++) {
            int i = (lane << 3) + r;
            s += q[b * H_ + i] * W[H_ + i];
        }
#pragma unroll
        for (int o = 16; o; o >>= 1)
            s += __shfl_xor_sync(FULLMASK, s, o);
        if (lane == 0) s_cb = s;
    }
    __syncthreads();   // barrier B

    // ---- warps 0..4: sort selected row k=wid, dot with W[:H] ----
    if (wid < K_) {
        const int k = wid;
        bool valid  = (s_tval[k] > NI);
        int  node   = s_tidx[k];
        const float* row = h + ((size_t)b * N_ + node) * H_;

        // element v = lane*8 + r lives in val[r] of this lane
        float val[8];
#pragma unroll
        for (int r = 0; r < 8; r++)
            val[r] = valid ? row[(lane << 3) + r] : 0.0f;

        // ---- register bitonic sort, 256 elements, ascending ----
#pragma unroll
        for (int kk = 2; kk <= 256; kk <<= 1) {
#pragma unroll
            for (int j = kk >> 1; j > 0; j >>= 1) {
                if (j >= 8) {
                    int  ld  = j >> 3;
                    bool asc = (((lane << 3) & kk) == 0);
                    bool low = ((lane & ld) == 0);
#pragma unroll
                    for (int r = 0; r < 8; r++) {
                        float other = __shfl_xor_sync(FULLMASK, val[r], ld);
                        val[r] = (low == asc) ? fminf(val[r], other)
                                              : fmaxf(val[r], other);
                    }
                } else {
#pragma unroll
                    for (int r = 0; r < 8; r++) {
                        if ((r & j) == 0) {
                            int  r2  = r | j;
                            bool asc = ((((lane << 3) | r) & kk) == 0);
                            float a = val[r], c = val[r2];
                            float lo = fminf(a, c), hi = fmaxf(a, c);
                            val[r]  = asc ? lo : hi;
                            val[r2] = asc ? hi : lo;
                        }
                    }
                }
            }
        }

        // store sorted row + dot with W[:H]
        float s = 0.0f;
#pragma unroll
        for (int r = 0; r < 8; r++) {
            int i = (lane << 3) + r;
            s_sel[k][i] = val[r];
            s += val[r] * W[i];
        }
#pragma unroll
        for (int o = 16; o; o >>= 1)
            s += __shfl_xor_sync(FULLMASK, s, o);
        if (lane == 0) {
            float x = s + s_cb;
            s_logit[k] = (x >= 0.0f) ? x : NEG_SLOPE * x;
        }
    }
    __syncthreads();   // barrier C

    // ---- softmax over K and weighted sum (thread t owns channel t) ----
    float lg[K_];
#pragma unroll
    for (int k = 0; k < K_; k++) lg[k] = s_logit[k];
    float lm = lg[0];
#pragma unroll
    for (int k = 1; k < K_; k++) lm = fmaxf(lm, lg[k]);
    float es = 0.0f;
    float e[K_];
#pragma unroll
    for (int k = 0; k < K_; k++) { e[k] = __expf(lg[k] - lm); es += e[k]; }
    float inv = 1.0f / es;
    float acc = 0.0f;
#pragma unroll
    for (int k = 0; k < K_; k++) acc += (e[k] * inv) * s_sel[k][t];

    out[b * H_ + t] = acc;
}

extern "C" void kernel_launch(void* const* d_in, const int* in_sizes, int n_in,
                              void* d_out, int out_size) {
    const float* h  = (const float*)d_in[0];           // [B, N, H]
    const int*   nn = (const int*)d_in[1];             // [B]
    const float* q  = (const float*)d_in[2];           // [B, H]
    const float* W  = (const float*)d_in[3];           // [1, 2H]
    float*       o  = (float*)d_out;                   // [B, H]

    (void)in_sizes; (void)n_in; (void)out_size;

    // Kernel 1: 4 nodes per warp, 8 warps/block -> 32 nodes/block
    node_max_kernel<<<(B_ * N_) / 32, 256>>>(h, nn);
    // Kernel 2: one block per batch
    pool_attn_kernel<<<B_, 256>>>(h, q, W, o);
}